// round 6
// baseline (speedup 1.0000x reference)
#include <cuda_runtime.h>
#include <cuda_bf16.h>

// Single-pass RWKV WKV scan, decoupled lookback over T-segments.
// R5: SEG 32->16 + __launch_bounds__(256,4) to double occupancy (the R3
// profile showed DRAM 45% / occ 24% -> latency-bound on register pressure).
//
// Per segment (normalized by running decay, product cancels in output):
//   cw_i = sum w_j ; e_i = exp(k_i - cw_i) ; ah_i = sum e ; bh_i = sum e*v
//   out_i = (b0 + bh_i) / (a0 + ah_i)
//   inclusive prefix: exp(cw_end) * (a0 + ah_end), same for b.

#define BATCH 16
#define TLEN  2048
#define DIM   1024
#define CHAN  (BATCH * DIM)     // 16384
#define SEG   16
#define NSEG  (TLEN / SEG)      // 128
#define BLKC  256               // channels per block
#define NCG   (CHAN / BLKC)     // 64

__device__ float    g_prefA[NSEG * CHAN];
__device__ float    g_prefB[NSEG * CHAN];
__device__ unsigned g_flag [NSEG * NCG];

__global__ void wkv_reset_flags() {
    const int i = blockIdx.x * blockDim.x + threadIdx.x;
    if (i < NSEG * NCG) g_flag[i] = 0u;
}

__global__ __launch_bounds__(BLKC, 4)
void wkv_fused(const float* __restrict__ K,
               const float* __restrict__ V,
               const float* __restrict__ W,
               float* __restrict__ O) {
    const int s   = blockIdx.x / NCG;     // segment (segment-major order)
    const int cg  = blockIdx.x % NCG;     // channel group
    const int tid = threadIdx.x;
    const int c   = cg * BLKC + tid;      // channel 0..16383
    const int b   = c >> 10;              // / DIM
    const int d   = c & (DIM - 1);        // % DIM

    const size_t base = (size_t)b * TLEN * DIM + (size_t)(s * SEG) * DIM + d;
    const float* kp = K + base;
    const float* vp = V + base;
    const float* wp = W + base;
    float*       op = O + base;

    // Local normalized scan: one exp per step, 2 x SEG register arrays.
    float ah[SEG], bh[SEG];
    float cw = 0.0f, aa = 0.0f, bb = 0.0f;
#pragma unroll
    for (int i = 0; i < SEG; ++i) {
        const float ki = kp[i * DIM];
        const float vi = vp[i * DIM];
        const float wi = wp[i * DIM];
        cw += wi;
        const float e = __expf(ki - cw);
        aa += e;
        bb = fmaf(e, vi, bb);
        ah[i] = aa;
        bh[i] = bb;
    }
    const float P = __expf(cw);

    // ---- lookback: wait for inclusive prefix of segment s-1 ----
    float a0 = 0.0f, b0 = 0.0f;
    if (s > 0) {
        if (tid == 0) {
            while (atomicAdd(&g_flag[(s - 1) * NCG + cg], 0u) == 0u)
                __nanosleep(40);
            __threadfence();   // acquire
        }
        __syncthreads();
        a0 = g_prefA[(size_t)(s - 1) * CHAN + c];
        b0 = g_prefB[(size_t)(s - 1) * CHAN + c];
    }

    // ---- publish inclusive prefix ASAP (chain critical path) ----
    g_prefA[(size_t)s * CHAN + c] = P * (a0 + aa);
    g_prefB[(size_t)s * CHAN + c] = P * (b0 + bb);
    __threadfence();           // release
    __syncthreads();
    if (tid == 0) atomicExch(&g_flag[s * NCG + cg], 1u);

    // ---- outputs (off the chain critical path) ----
#pragma unroll
    for (int i = 0; i < SEG; ++i)
        op[i * DIM] = __fdividef(b0 + bh[i], a0 + ah[i]);
}

extern "C" void kernel_launch(void* const* d_in, const int* in_sizes, int n_in,
                              void* d_out, int out_size) {
    const float* K = (const float*)d_in[0];
    const float* V = (const float*)d_in[1];
    const float* W = (const float*)d_in[2];
    float*       O = (float*)d_out;

    wkv_reset_flags<<<(NSEG * NCG + 255) / 256, 256>>>();
    wkv_fused<<<NSEG * NCG, BLKC>>>(K, V, W, O);   // 8192 blocks, segment-major
}

// round 7
// speedup vs baseline: 2.7808x; 2.7808x over previous
#include <cuda_runtime.h>
#include <cuda_bf16.h>

// Single-pass WKV scan, decoupled lookback, intra-block sub-segment scan.
//
// Block = 256 threads = 32 channels x 8 sub-segments of 16 timesteps
//   -> block covers 128 timesteps; global chain NSEG = 2048/128 = 16 hops.
//
// Thread-local (normalized by running decay; product cancels in out=b/a):
//   cw_i = sum w ; e_i = exp(k_i - cw_i) ; ah_i = sum e ; bh_i = sum e*v
// Sub-segment absolute affine map:  a_out = P*a_in + Qa,  P=exp(cw_end),
//   Qa = P*aa, Qb = P*bb.
// Warp 0 composes the 8 maps per channel -> exclusive (beta_j, alA_j, alB_j)
// with  A_in_j = alA_j + beta_j * a0   (linear in a0 -> computable pre-lookback).
// Lookback supplies (a0,b0) of segment s-1; publish inclusive prefix; then
//   out_i = (B_in + bh_i) / (A_in + ah_i).

#define BATCH  16
#define TLEN   2048
#define DIM    1024
#define CHAN   (BATCH * DIM)       // 16384
#define NCH    32                  // channels per block
#define NSUB   8                   // sub-segments per block
#define SUBSEG 16                  // timesteps per thread
#define SEGT   (NSUB * SUBSEG)     // 128 timesteps per block
#define NSEG   (TLEN / SEGT)       // 16 global segments
#define NCG    (CHAN / NCH)        // 512 channel groups
#define BLKT   (NCH * NSUB)        // 256 threads

__device__ float    g_prefA[NSEG * CHAN];
__device__ float    g_prefB[NSEG * CHAN];
__device__ unsigned g_flag [NSEG * NCG];

__global__ void wkv_reset_flags() {
    const int i = blockIdx.x * blockDim.x + threadIdx.x;
    if (i < NSEG * NCG) g_flag[i] = 0u;
}

__global__ __launch_bounds__(BLKT, 4)
void wkv_fused(const float* __restrict__ K,
               const float* __restrict__ V,
               const float* __restrict__ W,
               float* __restrict__ O) {
    const int s    = blockIdx.x / NCG;      // global segment (segment-major)
    const int cg   = blockIdx.x % NCG;      // channel group
    const int tid  = threadIdx.x;
    const int lane = tid & (NCH - 1);       // channel within group
    const int sub  = tid >> 5;              // sub-segment 0..7
    const int c    = cg * NCH + lane;       // global channel
    const int b    = c >> 10;               // / DIM
    const int d    = c & (DIM - 1);         // % DIM

    // smem: per-(sub,chan) aggregates + exclusive prefixes + chain state
    __shared__ float sP [NSUB][NCH], sQa[NSUB][NCH], sQb[NSUB][NCH];
    __shared__ float sBt[NSUB][NCH], sAl[NSUB][NCH], sBl[NSUB][NCH];
    __shared__ float sA0[NCH], sB0[NCH];

    const int t0 = s * SEGT + sub * SUBSEG;
    const size_t base = (size_t)b * TLEN * DIM + (size_t)t0 * DIM + d;
    const float* kp = K + base;
    const float* vp = V + base;
    const float* wp = W + base;
    float*       op = O + base;

    // ---- thread-local normalized scan (16 steps) ----
    float ah[SUBSEG], bh[SUBSEG];
    float cw = 0.0f, aa = 0.0f, bb = 0.0f;
#pragma unroll
    for (int i = 0; i < SUBSEG; ++i) {
        const float ki = kp[i * DIM];
        const float vi = vp[i * DIM];
        const float wi = wp[i * DIM];
        cw += wi;
        const float e = __expf(ki - cw);
        aa += e;
        bb = fmaf(e, vi, bb);
        ah[i] = aa;
        bh[i] = bb;
    }
    const float P = __expf(cw);
    sP [sub][lane] = P;
    sQa[sub][lane] = P * aa;
    sQb[sub][lane] = P * bb;
    __syncthreads();

    // ---- warp 0: compose 8 sub-segment maps per channel (pre-lookback),
    //      then lookback + publish ----
    if (tid < NCH) {
        float beta = 1.0f, alA = 0.0f, alB = 0.0f;
#pragma unroll
        for (int j = 0; j < NSUB; ++j) {
            sBt[j][tid] = beta;
            sAl[j][tid] = alA;
            sBl[j][tid] = alB;
            const float p = sP[j][tid];
            beta = p * beta;
            alA  = fmaf(p, alA, sQa[j][tid]);
            alB  = fmaf(p, alB, sQb[j][tid]);
        }

        float a0 = 0.0f, b0 = 0.0f;
        if (s > 0) {
            volatile unsigned* f = &g_flag[(s - 1) * NCG + cg];
            while (*f == 0u) __nanosleep(40);
            __threadfence();   // acquire (per-thread: orders the loads below)
            a0 = g_prefA[(size_t)(s - 1) * CHAN + c];
            b0 = g_prefB[(size_t)(s - 1) * CHAN + c];
        }
        sA0[tid] = a0;
        sB0[tid] = b0;

        // inclusive prefix of this segment
        g_prefA[(size_t)s * CHAN + c] = fmaf(beta, a0, alA);
        g_prefB[(size_t)s * CHAN + c] = fmaf(beta, b0, alB);
        __threadfence();       // release
        __syncwarp(0xFFFFFFFFu);
        if (tid == 0) atomicExch(&g_flag[s * NCG + cg], 1u);
    }
    __syncthreads();

    // ---- outputs ----
    const float beta = sBt[sub][lane];
    const float A_in = fmaf(beta, sA0[lane], sAl[sub][lane]);
    const float B_in = fmaf(beta, sB0[lane], sBl[sub][lane]);
#pragma unroll
    for (int i = 0; i < SUBSEG; ++i)
        op[i * DIM] = __fdividef(B_in + bh[i], A_in + ah[i]);
}

extern "C" void kernel_launch(void* const* d_in, const int* in_sizes, int n_in,
                              void* d_out, int out_size) {
    const float* K = (const float*)d_in[0];
    const float* V = (const float*)d_in[1];
    const float* W = (const float*)d_in[2];
    float*       O = (float*)d_out;

    wkv_reset_flags<<<(NSEG * NCG + 255) / 256, 256>>>();
    wkv_fused<<<NSEG * NCG, BLKT>>>(K, V, W, O);   // 8192 blocks, segment-major
}